// round 5
// baseline (speedup 1.0000x reference)
#include <cuda_runtime.h>
#include <cuda_bf16.h>
#include <math.h>

// ---------------- problem constants ----------------
#define BB   16
#define NN   2048
#define DD   1024
#define HH   8
#define DHD  64
#define II   512           // H*DH
#define LQ   64
#define SSQ  2112          // N + L
#define NDEPTH 6
#define FFD  4096

typedef __nv_bfloat16 bf16;

// ---------------- scratch ----------------
__device__ bf16 g_xh[(size_t)BB * NN * DD];
__device__ bf16 g_xl[(size_t)BB * NN * DD];
__device__ bf16 g_lnlh[BB * LQ * DD],  g_lnll[BB * LQ * DD];
__device__ bf16 g_lnfh[BB * LQ * DD],  g_lnfl[BB * LQ * DD];
__device__ bf16 g_atth[BB * LQ * II],  g_attl[BB * LQ * II];
__device__ bf16 g_hfh [BB * LQ * FFD], g_hfl [BB * LQ * FFD];
__device__ bf16 g_wqh [DD * II],       g_wql [DD * II];
__device__ bf16 g_wkvh[DD * 2 * II],   g_wkvl[DD * 2 * II];
__device__ bf16 g_wkvph[DD * 2 * II],  g_wkvpl[DD * 2 * II];
__device__ bf16 g_woh [II * DD],       g_wol [II * DD];
__device__ bf16 g_w1h [DD * FFD],      g_w1l [DD * FFD];
__device__ bf16 g_w2h [FFD * DD],      g_w2l [FFD * DD];
__device__ float g_lat[BB * LQ * DD];
__device__ float g_q  [BB * LQ * II];
__device__ float g_k  [(size_t)BB * HH * SSQ * DHD];
__device__ float g_v  [(size_t)BB * HH * SSQ * DHD];
__device__ float g_biaskv[2 * II];

// ---------------- helpers ----------------
__device__ __forceinline__ unsigned pack2(float x, float y)
{
    bf16 hx = __float2bfloat16_rn(x);
    bf16 hy = __float2bfloat16_rn(y);
    return (unsigned)__bfloat16_as_ushort(hx) | ((unsigned)__bfloat16_as_ushort(hy) << 16);
}
__device__ __forceinline__ void split4(float4 v, uint2& hi, uint2& lo)
{
    float hx = __bfloat162float(__float2bfloat16_rn(v.x));
    float hy = __bfloat162float(__float2bfloat16_rn(v.y));
    float hz = __bfloat162float(__float2bfloat16_rn(v.z));
    float hw = __bfloat162float(__float2bfloat16_rn(v.w));
    hi = make_uint2(pack2(v.x, v.y), pack2(v.z, v.w));
    lo = make_uint2(pack2(v.x - hx, v.y - hy), pack2(v.z - hz, v.w - hw));
}

// ---------------- LayerNorm (fp32 out, final layer) ----------------
__global__ __launch_bounds__(256) void ln_kernel(const float* __restrict__ in,
                                                 float* __restrict__ out,
                                                 const float* __restrict__ w,
                                                 const float* __restrict__ b)
{
    int row = blockIdx.x;
    int tid = threadIdx.x;
    const float4 xv = *(const float4*)(in + (size_t)row * DD + tid * 4);
    float s  = xv.x + xv.y + xv.z + xv.w;
    float ss = xv.x * xv.x + xv.y * xv.y + xv.z * xv.z + xv.w * xv.w;
    #pragma unroll
    for (int o = 16; o; o >>= 1) {
        s  += __shfl_xor_sync(0xffffffffu, s,  o);
        ss += __shfl_xor_sync(0xffffffffu, ss, o);
    }
    __shared__ float red[16];
    int wid = tid >> 5;
    if ((tid & 31) == 0) { red[wid] = s; red[wid + 8] = ss; }
    __syncthreads();
    s = 0.f; ss = 0.f;
    #pragma unroll
    for (int i = 0; i < 8; i++) { s += red[i]; ss += red[i + 8]; }
    float mu   = s * (1.f / DD);
    float var  = ss * (1.f / DD) - mu * mu;
    float rstd = rsqrtf(var + 1e-5f);
    float4 o4;
    o4.x = (xv.x - mu) * rstd; o4.y = (xv.y - mu) * rstd;
    o4.z = (xv.z - mu) * rstd; o4.w = (xv.w - mu) * rstd;
    const float4 wv = *(const float4*)(w + tid * 4);
    const float4 bv = *(const float4*)(b + tid * 4);
    o4.x = o4.x * wv.x + bv.x; o4.y = o4.y * wv.y + bv.y;
    o4.z = o4.z * wv.z + bv.z; o4.w = o4.w * wv.w + bv.w;
    *(float4*)(out + (size_t)row * DD + tid * 4) = o4;
}

// ---------------- LayerNorm -> split bf16 hi/lo ----------------
__global__ __launch_bounds__(256) void ln_split_kernel(const float* __restrict__ in,
                                                       bf16* __restrict__ hi,
                                                       bf16* __restrict__ lo,
                                                       const float* __restrict__ w,
                                                       const float* __restrict__ b)
{
    int row = blockIdx.x;
    int tid = threadIdx.x;
    const float4 xv = *(const float4*)(in + (size_t)row * DD + tid * 4);
    float s  = xv.x + xv.y + xv.z + xv.w;
    float ss = xv.x * xv.x + xv.y * xv.y + xv.z * xv.z + xv.w * xv.w;
    #pragma unroll
    for (int o = 16; o; o >>= 1) {
        s  += __shfl_xor_sync(0xffffffffu, s,  o);
        ss += __shfl_xor_sync(0xffffffffu, ss, o);
    }
    __shared__ float red[16];
    int wid = tid >> 5;
    if ((tid & 31) == 0) { red[wid] = s; red[wid + 8] = ss; }
    __syncthreads();
    s = 0.f; ss = 0.f;
    #pragma unroll
    for (int i = 0; i < 8; i++) { s += red[i]; ss += red[i + 8]; }
    float mu   = s * (1.f / DD);
    float var  = ss * (1.f / DD) - mu * mu;
    float rstd = rsqrtf(var + 1e-5f);
    float4 o4;
    o4.x = (xv.x - mu) * rstd; o4.y = (xv.y - mu) * rstd;
    o4.z = (xv.z - mu) * rstd; o4.w = (xv.w - mu) * rstd;
    if (w) {
        const float4 wv = *(const float4*)(w + tid * 4);
        const float4 bv = *(const float4*)(b + tid * 4);
        o4.x = o4.x * wv.x + bv.x; o4.y = o4.y * wv.y + bv.y;
        o4.z = o4.z * wv.z + bv.z; o4.w = o4.w * wv.w + bv.w;
    }
    uint2 h, l;
    split4(o4, h, l);
    *(uint2*)(hi + (size_t)row * DD + tid * 4) = h;
    *(uint2*)(lo + (size_t)row * DD + tid * 4) = l;
}

// ---------------- generic split (weights), optional per-row(1024) scale ------
__global__ __launch_bounds__(256) void split_kernel(const float* __restrict__ in,
                                                    const float* __restrict__ rowscale,
                                                    bf16* __restrict__ hi,
                                                    bf16* __restrict__ lo)
{
    int idx = (blockIdx.x * 256 + threadIdx.x) * 4;
    float4 v = *(const float4*)(in + idx);
    if (rowscale) {
        float sc = rowscale[idx >> 10];
        v.x *= sc; v.y *= sc; v.z *= sc; v.w *= sc;
    }
    uint2 h, l;
    split4(v, h, l);
    *(uint2*)(hi + idx) = h;
    *(uint2*)(lo + idx) = l;
}

// ---------------- lat init ----------------
__global__ void init_lat_kernel(const float* __restrict__ latents, float* __restrict__ lat)
{
    int idx = blockIdx.x * 256 + threadIdx.x;
    lat[idx] = latents[idx & (LQ * DD - 1)];
}

// ---------------- biaskv[j] = sum_d ln_m_b[d] * Wkv[d][j] ----------------
__global__ void bias_kv_kernel(const float* __restrict__ Wkv, const float* __restrict__ lnb,
                               float* __restrict__ bias)
{
    int j  = blockIdx.x * 32 + (threadIdx.x & 31);
    int dc = threadIdx.x >> 5;
    float a = 0.f;
    int d0 = dc * 128;
    #pragma unroll 8
    for (int d = d0; d < d0 + 128; d++) a += lnb[d] * Wkv[(size_t)d * 1024 + j];
    __shared__ float red[8][32];
    red[dc][threadIdx.x & 31] = a;
    __syncthreads();
    if (dc == 0) {
        float s = 0.f;
        #pragma unroll
        for (int i = 0; i < 8; i++) s += red[i][threadIdx.x & 31];
        bias[j] = s;
    }
}

// ================= bf16x3 split-precision tensor-core GEMM =================
enum { EPI_NONE = 0, EPI_ADD = 1, EPI_GELU = 2, EPI_KV = 3 };

#define GBK 32
#define AST 40
#define BST 136

__device__ __forceinline__ void mma16816(float* d, const unsigned* a, const unsigned* b)
{
    asm volatile(
        "mma.sync.aligned.m16n8k16.row.col.f32.bf16.bf16.f32 "
        "{%0,%1,%2,%3}, {%4,%5,%6,%7}, {%8,%9}, {%0,%1,%2,%3};\n"
        : "+f"(d[0]), "+f"(d[1]), "+f"(d[2]), "+f"(d[3])
        : "r"(a[0]), "r"(a[1]), "r"(a[2]), "r"(a[3]), "r"(b[0]), "r"(b[1]));
}
__device__ __forceinline__ void ldsm4(unsigned* r, unsigned addr)
{
    asm volatile("ldmatrix.sync.aligned.m8n8.x4.shared.b16 {%0,%1,%2,%3}, [%4];\n"
                 : "=r"(r[0]), "=r"(r[1]), "=r"(r[2]), "=r"(r[3]) : "r"(addr));
}
__device__ __forceinline__ void ldsm4t(unsigned* r, unsigned addr)
{
    asm volatile("ldmatrix.sync.aligned.m8n8.x4.trans.shared.b16 {%0,%1,%2,%3}, [%4];\n"
                 : "=r"(r[0]), "=r"(r[1]), "=r"(r[2]), "=r"(r[3]) : "r"(addr));
}
__device__ __forceinline__ void cpasync16(unsigned s, const void* g)
{
    asm volatile("cp.async.cg.shared.global [%0], [%1], 16;\n" :: "r"(s), "l"(g));
}
#define CP_COMMIT() asm volatile("cp.async.commit_group;\n")
#define CP_WAIT1()  asm volatile("cp.async.wait_group 1;\n")

template<int TM>
__global__ __launch_bounds__(256) void gemm_bf16(
    const bf16* __restrict__ Ahi, const bf16* __restrict__ Alo,
    const bf16* __restrict__ Bhi, const bf16* __restrict__ Blo,
    float* __restrict__ C, int M, int N, int K, int epi,
    const float* __restrict__ bias,
    float* __restrict__ Kout, float* __restrict__ Vout, int rowsPerB, int sBase,
    bf16* __restrict__ OutHi, bf16* __restrict__ OutLo)
{
    constexpr int WM16   = TM / 32;
    constexpr int A_EL   = TM * AST;
    constexpr int B_EL   = GBK * BST;
    constexpr int STAGE  = 2 * A_EL + 2 * B_EL;      // elements per stage
    extern __shared__ __align__(16) bf16 smg[];
    unsigned base = (unsigned)__cvta_generic_to_shared(smg);

    int tid  = threadIdx.x;
    int lane = tid & 31;
    int warp = tid >> 5;
    int wm = warp & 1, wn = warp >> 1;
    int row0 = blockIdx.y * TM;
    int col0 = blockIdx.x << 7;
    int lr = (lane & 7) + (((lane >> 3) & 1) << 3);
    int lc = (lane >> 4) << 3;

    float acc[WM16][4][4];
    #pragma unroll
    for (int i = 0; i < WM16; i++)
        #pragma unroll
        for (int j = 0; j < 4; j++)
            #pragma unroll
            for (int t = 0; t < 4; t++) acc[i][j][t] = 0.f;

    auto load_stage = [&](int kt, int buf) {
        unsigned sb = base + (unsigned)buf * STAGE * 2;
        constexpr int ACH = (TM * 4) / 256;
        #pragma unroll
        for (int p = 0; p < 2; p++) {
            const bf16* Ap = p ? Alo : Ahi;
            unsigned so = sb + (unsigned)p * A_EL * 2;
            #pragma unroll
            for (int i = 0; i < ACH; i++) {
                int chunk = tid + i * 256;
                int r = chunk >> 2, c16 = chunk & 3;
                cpasync16(so + (unsigned)(r * AST + c16 * 8) * 2,
                          Ap + (size_t)(row0 + r) * K + kt + c16 * 8);
            }
        }
        #pragma unroll
        for (int p = 0; p < 2; p++) {
            const bf16* Bp = p ? Blo : Bhi;
            unsigned so = sb + (unsigned)(2 * A_EL + p * B_EL) * 2;
            #pragma unroll
            for (int i = 0; i < 2; i++) {
                int chunk = tid + i * 256;
                int r = chunk >> 4, cc = (chunk & 15) * 8;
                cpasync16(so + (unsigned)(r * BST + cc) * 2,
                          Bp + (size_t)(kt + r) * N + col0 + cc);
            }
        }
    };

    int NK = K / GBK;
    load_stage(0, 0);   CP_COMMIT();
    load_stage(GBK, 1); CP_COMMIT();

    for (int it = 0; it < NK; it++) {
        CP_WAIT1();
        __syncthreads();
        unsigned sb  = base + (unsigned)(it & 1) * STAGE * 2;
        unsigned aHi = sb;
        unsigned aLo = sb + A_EL * 2;
        unsigned bHi = sb + 2 * A_EL * 2;
        unsigned bLo = bHi + B_EL * 2;

        #pragma unroll
        for (int k16 = 0; k16 < GBK; k16 += 16) {
            unsigned ah[WM16][4], al[WM16][4], bh[2][4], bl[2][4];
            #pragma unroll
            for (int mi = 0; mi < WM16; mi++) {
                unsigned off = (unsigned)((wm * (TM / 2) + mi * 16 + lr) * AST + k16 + lc) * 2;
                ldsm4(ah[mi], aHi + off);
                ldsm4(al[mi], aLo + off);
            }
            #pragma unroll
            for (int ni = 0; ni < 2; ni++) {
                unsigned off = (unsigned)((k16 + lr) * BST + wn * 32 + ni * 16 + lc) * 2;
                ldsm4t(bh[ni], bHi + off);
                ldsm4t(bl[ni], bLo + off);
            }
            #pragma unroll
            for (int mi = 0; mi < WM16; mi++) {
                #pragma unroll
                for (int nj = 0; nj < 4; nj++) {
                    int ni = nj >> 1, p = nj & 1;
                    mma16816(acc[mi][nj], ah[mi], &bh[ni][2 * p]);
                    mma16816(acc[mi][nj], ah[mi], &bl[ni][2 * p]);
                    mma16816(acc[mi][nj], al[mi], &bh[ni][2 * p]);
                }
            }
        }
        __syncthreads();
        if (it + 2 < NK) load_stage((it + 2) * GBK, it & 1);
        CP_COMMIT();
    }

    // ---------------- epilogue ----------------
    int rbase = row0 + wm * (TM / 2) + (lane >> 2);
    int cbase = col0 + wn * 32 + (lane & 3) * 2;
    #pragma unroll
    for (int mi = 0; mi < WM16; mi++) {
        #pragma unroll
        for (int nj = 0; nj < 4; nj++) {
            #pragma unroll
            for (int half = 0; half < 2; half++) {
                int r = rbase + mi * 16 + half * 8;
                int c = cbase + nj * 8;
                float v0 = acc[mi][nj][half * 2 + 0];
                float v1 = acc[mi][nj][half * 2 + 1];
                if (epi == EPI_KV) {
                    if (bias) { v0 += bias[c]; v1 += bias[c + 1]; }
                    int bb = r / rowsPerB;
                    int s  = sBase + (r - bb * rowsPerB);
                    float* dst;
                    if (c < II)
                        dst = Kout + (((size_t)bb * HH + (c >> 6)) * SSQ + s) * DHD + (c & 63);
                    else
                        dst = Vout + (((size_t)bb * HH + ((c - II) >> 6)) * SSQ + s) * DHD + ((c - II) & 63);
                    dst[0] = v0; dst[1] = v1;
                } else if (epi == EPI_GELU) {
                    float h0 = 0.5f * v0 * (1.f + erff(v0 * 0.70710678118654752f));
                    float h1 = 0.5f * v1 * (1.f + erff(v1 * 0.70710678118654752f));
                    float t0 = __bfloat162float(__float2bfloat16_rn(h0));
                    float t1 = __bfloat162float(__float2bfloat16_rn(h1));
                    *(unsigned*)(OutHi + (size_t)r * N + c) = pack2(h0, h1);
                    *(unsigned*)(OutLo + (size_t)r * N + c) = pack2(h0 - t0, h1 - t1);
                } else {
                    float* dst = C + (size_t)r * N + c;
                    if (epi == EPI_ADD) { v0 += dst[0]; v1 += dst[1]; }
                    dst[0] = v0; dst[1] = v1;
                }
            }
        }
    }
}

// ---------------- fused flash attention v2 ----------------
// 2 CTAs per (b,h): each handles 32 q rows, all S. K stored d-major in smem.
#define AT2  68
#define ATTN_SMEM (((size_t)(32 + 64 + 64 + 32) * AT2 + 64) * 4)

__global__ __launch_bounds__(256) void attn_kernel(
    const float* __restrict__ q, const float* __restrict__ kg, const float* __restrict__ vg,
    const int* __restrict__ mask, bf16* __restrict__ attHi, bf16* __restrict__ attLo)
{
    extern __shared__ float sm[];
    float* qs  = sm;                              // [32][AT2] : q rows, d cols
    float* kT  = sm + 32 * AT2;                   // [64][AT2] : kT[d][s]
    float* vs  = sm + (32 + 64) * AT2;            // [64][AT2] : v rows s, d cols
    float* ps  = sm + (32 + 128) * AT2;           // [32][AT2]
    float* msk = sm + (32 + 160) * AT2;           // [64]

    int blk = blockIdx.x;
    int bh = blk >> 1, half = blk & 1;
    int b = bh >> 3, h = bh & 7;
    int tid = threadIdx.x;
    int qr = tid >> 3;                 // 0..31
    int j0 = (tid & 7) * 8;            // this thread's 8 score cols / 8 dh cols

    const float* qbase = q + ((size_t)(b * LQ) + half * 32) * II + h * DHD;
    for (int idx = tid; idx < 32 * 16; idx += 256) {
        int r = idx >> 4, d4 = (idx & 15) << 2;
        *(float4*)&qs[r * AT2 + d4] = *(const float4*)&qbase[(size_t)r * II + d4];
    }

    float acc[8];
    #pragma unroll
    for (int i = 0; i < 8; i++) acc[i] = 0.f;
    float m = -1e30f, l = 0.f;

    const float* kb = kg + ((size_t)b * HH + h) * SSQ * DHD;
    const float* vb = vg + ((size_t)b * HH + h) * SSQ * DHD;
    const int* mrow = mask + b * NN;

    for (int t = 0; t < SSQ / 64; t++) {
        int s0 = t * 64;
        __syncthreads();
        for (int idx = tid; idx < 64 * 16; idx += 256) {
            int r = idx >> 4, d4 = (idx & 15) << 2;
            float4 k4 = *(const float4*)&kb[(size_t)(s0 + r) * DHD + d4];
            kT[(d4 + 0) * AT2 + r] = k4.x;
            kT[(d4 + 1) * AT2 + r] = k4.y;
            kT[(d4 + 2) * AT2 + r] = k4.z;
            kT[(d4 + 3) * AT2 + r] = k4.w;
            *(float4*)&vs[r * AT2 + d4] = *(const float4*)&vb[(size_t)(s0 + r) * DHD + d4];
        }
        if (tid < 64) {
            int s = s0 + tid;
            msk[tid] = (s < NN && mrow[s] == 1) ? 1.f : 0.f;
        }
        __syncthreads();

        float sc[8];
        #pragma unroll
        for (int j = 0; j < 8; j++) sc[j] = 0.f;
        const float* qrow = &qs[qr * AT2];
        #pragma unroll 8
        for (int d = 0; d < 64; d++) {
            float qv = qrow[d];
            float4 kA = *(const float4*)&kT[d * AT2 + j0];
            float4 kB = *(const float4*)&kT[d * AT2 + j0 + 4];
            sc[0] += qv * kA.x; sc[1] += qv * kA.y; sc[2] += qv * kA.z; sc[3] += qv * kA.w;
            sc[4] += qv * kB.x; sc[5] += qv * kB.y; sc[6] += qv * kB.z; sc[7] += qv * kB.w;
        }
        float tmax = -1e30f;
        #pragma unroll
        for (int j = 0; j < 8; j++) {
            float s = sc[j] * 0.125f;
            if (msk[j0 + j] != 0.f) s = -1e30f;
            sc[j] = s;
            tmax = fmaxf(tmax, s);
        }
        tmax = fmaxf(tmax, __shfl_xor_sync(0xffffffffu, tmax, 1));
        tmax = fmaxf(tmax, __shfl_xor_sync(0xffffffffu, tmax, 2));
        tmax = fmaxf(tmax, __shfl_xor_sync(0xffffffffu, tmax, 4));
        float mnew = fmaxf(m, tmax);
        float corr = __expf(m - mnew);
        float psum = 0.f;
        #pragma unroll
        for (int j = 0; j < 8; j++) {
            float p = __expf(sc[j] - mnew);
            ps[qr * AT2 + j0 + j] = p;
            psum += p;
        }
        psum += __shfl_xor_sync(0xffffffffu, psum, 1);
        psum += __shfl_xor_sync(0xffffffffu, psum, 2);
        psum += __shfl_xor_sync(0xffffffffu, psum, 4);
        l = l * corr + psum;
        m = mnew;
        #pragma unroll
        for (int i = 0; i < 8; i++) acc[i] *= corr;
        __syncwarp();

        #pragma unroll 4
        for (int j = 0; j < 64; j++) {
            float p = ps[qr * AT2 + j];
            float4 v0 = *(const float4*)&vs[j * AT2 + j0];
            float4 v1 = *(const float4*)&vs[j * AT2 + j0 + 4];
            acc[0] += p * v0.x; acc[1] += p * v0.y; acc[2] += p * v0.z; acc[3] += p * v0.w;
            acc[4] += p * v1.x; acc[5] += p * v1.y; acc[6] += p * v1.z; acc[7] += p * v1.w;
        }
    }

    float invl = 1.f / l;
    size_t obase = ((size_t)(b * LQ) + half * 32 + qr) * II + h * DHD + j0;
    float o[8];
    #pragma unroll
    for (int i = 0; i < 8; i++) o[i] = acc[i] * invl;
    float th[8];
    #pragma unroll
    for (int i = 0; i < 8; i++) th[i] = __bfloat162float(__float2bfloat16_rn(o[i]));
    *(uint2*)(attHi + obase)     = make_uint2(pack2(o[0], o[1]), pack2(o[2], o[3]));
    *(uint2*)(attHi + obase + 4) = make_uint2(pack2(o[4], o[5]), pack2(o[6], o[7]));
    *(uint2*)(attLo + obase)     = make_uint2(pack2(o[0]-th[0], o[1]-th[1]), pack2(o[2]-th[2], o[3]-th[3]));
    *(uint2*)(attLo + obase + 4) = make_uint2(pack2(o[4]-th[4], o[5]-th[5]), pack2(o[6]-th[6], o[7]-th[7]));
}

// ---------------- host orchestration ----------------
#define SMEM128 ((2 * (2 * 128 * AST + 2 * GBK * BST)) * 2)
#define SMEM64  ((2 * (2 * 64  * AST + 2 * GBK * BST)) * 2)

extern "C" void kernel_launch(void* const* d_in, const int* in_sizes, int n_in,
                              void* d_out, int out_size)
{
    (void)in_sizes; (void)n_in; (void)out_size;
    const float* x        = (const float*)d_in[0];
    const int*   mask     = (const int*)  d_in[1];
    const float* latents  = (const float*)d_in[2];
    const float* ln_m_w   = (const float*)d_in[3];
    const float* ln_m_b   = (const float*)d_in[4];
    const float* ln_l_w   = (const float*)d_in[5];
    const float* ln_l_b   = (const float*)d_in[6];
    const float* Wq       = (const float*)d_in[7];
    const float* Wkv      = (const float*)d_in[8];
    const float* Wo       = (const float*)d_in[9];
    const float* ff_ln_w  = (const float*)d_in[10];
    const float* ff_ln_b  = (const float*)d_in[11];
    const float* W1       = (const float*)d_in[12];
    const float* W2       = (const float*)d_in[13];
    const float* norm_w   = (const float*)d_in[14];
    const float* norm_b   = (const float*)d_in[15];
    float* out = (float*)d_out;

    bf16 *xh, *xl, *lnlh, *lnll, *lnfh, *lnfl, *atth, *attl, *hfh, *hfl;
    bf16 *wqh, *wql, *wkvh, *wkvl, *wkvph, *wkvpl, *woh, *wol, *w1h, *w1l, *w2h, *w2l;
    float *lat, *qb, *kb, *vb, *biaskv;
    cudaGetSymbolAddress((void**)&xh, g_xh);     cudaGetSymbolAddress((void**)&xl, g_xl);
    cudaGetSymbolAddress((void**)&lnlh, g_lnlh); cudaGetSymbolAddress((void**)&lnll, g_lnll);
    cudaGetSymbolAddress((void**)&lnfh, g_lnfh); cudaGetSymbolAddress((void**)&lnfl, g_lnfl);
    cudaGetSymbolAddress((void**)&atth, g_atth); cudaGetSymbolAddress((void**)&attl, g_attl);
    cudaGetSymbolAddress((void**)&hfh, g_hfh);   cudaGetSymbolAddress((void**)&hfl, g_hfl);
    cudaGetSymbolAddress((void**)&wqh, g_wqh);   cudaGetSymbolAddress((void**)&wql, g_wql);
    cudaGetSymbolAddress((void**)&wkvh, g_wkvh); cudaGetSymbolAddress((void**)&wkvl, g_wkvl);
    cudaGetSymbolAddress((void**)&wkvph, g_wkvph); cudaGetSymbolAddress((void**)&wkvpl, g_wkvpl);
    cudaGetSymbolAddress((void**)&woh, g_woh);   cudaGetSymbolAddress((void**)&wol, g_wol);
    cudaGetSymbolAddress((void**)&w1h, g_w1h);   cudaGetSymbolAddress((void**)&w1l, g_w1l);
    cudaGetSymbolAddress((void**)&w2h, g_w2h);   cudaGetSymbolAddress((void**)&w2l, g_w2l);
    cudaGetSymbolAddress((void**)&lat, g_lat);
    cudaGetSymbolAddress((void**)&qb, g_q);
    cudaGetSymbolAddress((void**)&kb, g_k);
    cudaGetSymbolAddress((void**)&vb, g_v);
    cudaGetSymbolAddress((void**)&biaskv, g_biaskv);

    cudaFuncSetAttribute(gemm_bf16<128>, cudaFuncAttributeMaxDynamicSharedMemorySize, SMEM128);
    cudaFuncSetAttribute(gemm_bf16<64>,  cudaFuncAttributeMaxDynamicSharedMemorySize, SMEM64);
    cudaFuncSetAttribute(attn_kernel,    cudaFuncAttributeMaxDynamicSharedMemorySize, (int)ATTN_SMEM);

    // layer-invariant
    ln_split_kernel<<<BB * NN, 256>>>(x, xh, xl, nullptr, nullptr);
    init_lat_kernel<<<BB * LQ * DD / 256, 256>>>(latents, lat);

    for (int i = 0; i < NDEPTH; i++) {
        const float* Wkv_i = Wkv + (size_t)i * DD * 2 * II;
        const float* Wq_i  = Wq  + (size_t)i * DD * II;
        const float* Wo_i  = Wo  + (size_t)i * II * DD;
        const float* W1_i  = W1  + (size_t)i * DD * FFD;
        const float* W2_i  = W2  + (size_t)i * FFD * DD;

        // weight conversions
        split_kernel<<<DD * 2 * II / 1024, 256>>>(Wkv_i, ln_m_w + i * DD, wkvph, wkvpl);
        split_kernel<<<DD * 2 * II / 1024, 256>>>(Wkv_i, nullptr, wkvh, wkvl);
        split_kernel<<<DD * II / 1024, 256>>>(Wq_i, nullptr, wqh, wql);
        split_kernel<<<II * DD / 1024, 256>>>(Wo_i, nullptr, woh, wol);
        split_kernel<<<DD * FFD / 1024, 256>>>(W1_i, nullptr, w1h, w1l);
        split_kernel<<<FFD * DD / 1024, 256>>>(W2_i, nullptr, w2h, w2l);
        bias_kv_kernel<<<32, 256>>>(Wkv_i, ln_m_b + i * DD, biaskv);

        ln_split_kernel<<<BB * LQ, 256>>>(lat, lnlh, lnll, ln_l_w + i * DD, ln_l_b + i * DD);

        // q = lnl @ Wq  (fp32 out)
        gemm_bf16<64><<<dim3(II / 128, BB * LQ / 64), 256, SMEM64>>>(
            lnlh, lnll, wqh, wql, qb, BB * LQ, II, DD, EPI_NONE,
            nullptr, nullptr, nullptr, 0, 0, nullptr, nullptr);

        // kv (x part)
        gemm_bf16<128><<<dim3(2 * II / 128, BB * NN / 128), 256, SMEM128>>>(
            xh, xl, wkvph, wkvpl, nullptr, BB * NN, 2 * II, DD, EPI_KV,
            biaskv, kb, vb, NN, 0, nullptr, nullptr);

        // kv (latent part)
        gemm_bf16<64><<<dim3(2 * II / 128, BB * LQ / 64), 256, SMEM64>>>(
            lnlh, lnll, wkvh, wkvl, nullptr, BB * LQ, 2 * II, DD, EPI_KV,
            nullptr, kb, vb, LQ, NN, nullptr, nullptr);

        // attention -> split bf16
        attn_kernel<<<BB * HH * 2, 256, ATTN_SMEM>>>(qb, kb, vb, mask, atth, attl);

        // lat += att @ Wo
        gemm_bf16<64><<<dim3(DD / 128, BB * LQ / 64), 256, SMEM64>>>(
            atth, attl, woh, wol, lat, BB * LQ, DD, II, EPI_ADD,
            nullptr, nullptr, nullptr, 0, 0, nullptr, nullptr);

        // FF
        ln_split_kernel<<<BB * LQ, 256>>>(lat, lnfh, lnfl, ff_ln_w + i * DD, ff_ln_b + i * DD);
        gemm_bf16<64><<<dim3(FFD / 128, BB * LQ / 64), 256, SMEM64>>>(
            lnfh, lnfl, w1h, w1l, nullptr, BB * LQ, FFD, DD, EPI_GELU,
            nullptr, nullptr, nullptr, 0, 0, hfh, hfl);
        gemm_bf16<64><<<dim3(DD / 128, BB * LQ / 64), 256, SMEM64>>>(
            hfh, hfl, w2h, w2l, lat, BB * LQ, DD, FFD, EPI_ADD,
            nullptr, nullptr, nullptr, 0, 0, nullptr, nullptr);
    }

    ln_kernel<<<BB * LQ, 256>>>(lat, out, norm_w, norm_b);
}